// round 1
// baseline (speedup 1.0000x reference)
#include <cuda_runtime.h>
#include <math.h>

#define Bn 4
#define Sn 2048
#define Dn 1024
#define Hn 16
#define DKn 64
#define Mn (Bn*Sn)

// Scratch (static device globals: allocation-free)
__device__ float g_q[(size_t)Bn*Hn*Sn*DKn];
__device__ float g_k[(size_t)Bn*Hn*Sn*DKn];
__device__ float g_v[(size_t)Bn*Hn*Sn*DKn];
__device__ float g_t[(size_t)Bn*Sn*Dn];

// ---------------------------------------------------------------------------
// C[m,n] = sum_k A[m,k] * W[n,k]   (A: [M,1024], W: [1024,1024], C: [M,1024])
// 128x128 tile, BK=8, 256 threads, 8x8 micro-tile
// ---------------------------------------------------------------------------
__global__ __launch_bounds__(256) void gemm_nt(const float* __restrict__ A,
                                               const float* __restrict__ W,
                                               float* __restrict__ C) {
    const int K = Dn;
    __shared__ float As[8][128];
    __shared__ float Ws[8][128];
    int tid = threadIdx.x;
    int tx = tid & 15, ty = tid >> 4;
    int mbase = blockIdx.y * 128, nbase = blockIdx.x * 128;
    int lrow = tid >> 1;
    int lc4  = (tid & 1) * 4;
    const float* Ap = A + (size_t)(mbase + lrow) * K + lc4;
    const float* Wp = W + (size_t)(nbase + lrow) * K + lc4;

    float acc[8][8];
#pragma unroll
    for (int i = 0; i < 8; i++)
#pragma unroll
        for (int j = 0; j < 8; j++) acc[i][j] = 0.f;

    for (int k0 = 0; k0 < K; k0 += 8) {
        float4 av = *(const float4*)(Ap + k0);
        float4 wv = *(const float4*)(Wp + k0);
        __syncthreads();
        As[lc4+0][lrow] = av.x; As[lc4+1][lrow] = av.y;
        As[lc4+2][lrow] = av.z; As[lc4+3][lrow] = av.w;
        Ws[lc4+0][lrow] = wv.x; Ws[lc4+1][lrow] = wv.y;
        Ws[lc4+2][lrow] = wv.z; Ws[lc4+3][lrow] = wv.w;
        __syncthreads();
#pragma unroll
        for (int kk = 0; kk < 8; kk++) {
            float a[8], b[8];
            *(float4*)&a[0] = *(const float4*)&As[kk][ty*8];
            *(float4*)&a[4] = *(const float4*)&As[kk][ty*8+4];
            *(float4*)&b[0] = *(const float4*)&Ws[kk][tx*8];
            *(float4*)&b[4] = *(const float4*)&Ws[kk][tx*8+4];
#pragma unroll
            for (int i = 0; i < 8; i++)
#pragma unroll
                for (int j = 0; j < 8; j++)
                    acc[i][j] = fmaf(a[i], b[j], acc[i][j]);
        }
    }

#pragma unroll
    for (int i = 0; i < 8; i++) {
        float* Cp = C + (size_t)(mbase + ty*8 + i) * Dn + nbase + tx*8;
        *(float4*)Cp     = make_float4(acc[i][0], acc[i][1], acc[i][2], acc[i][3]);
        *(float4*)(Cp+4) = make_float4(acc[i][4], acc[i][5], acc[i][6], acc[i][7]);
    }
}

// ---------------------------------------------------------------------------
// RoPE + head transpose: in [B,S,H,DK] -> out [B,H,S,DK], interleaved pairs
// ---------------------------------------------------------------------------
__global__ void rope_kernel(const float* __restrict__ in, float* __restrict__ out) {
    int p = blockIdx.x * blockDim.x + threadIdx.x;
    if (p >= Bn*Sn*Hn*32) return;
    int i = p & 31;             // pair index within head (0..31)
    int h = (p >> 5) & (Hn-1);
    int s = (p >> 9) & (Sn-1);
    int b = p >> 20;
    const float* src = in + ((size_t)((size_t)b*Sn + s)*Hn + h)*DKn + 2*i;
    float x1 = src[0], x2 = src[1];
    // inv_freq = 10000^(-(2i)/64)
    float freq = expf(-((float)(2*i) / (float)DKn) * 9.210340371976184f);
    float ang = (float)s * freq;
    float sn, cs;
    sincosf(ang, &sn, &cs);
    float* dst = out + ((size_t)((size_t)b*Hn + h)*Sn + s)*DKn + 2*i;
    dst[0] = x1*cs - x2*sn;
    dst[1] = x1*sn + x2*cs;
}

// ---------------------------------------------------------------------------
// V head transpose: [B,S,H,DK] -> [B,H,S,DK] (float4 granularity)
// ---------------------------------------------------------------------------
__global__ void vperm_kernel(const float4* __restrict__ in, float4* __restrict__ out) {
    int p = blockIdx.x * blockDim.x + threadIdx.x;
    if (p >= Bn*Sn*Hn*16) return;
    int c = p & 15;
    int h = (p >> 4) & 15;
    int s = (p >> 8) & 2047;
    int b = p >> 19;
    out[((size_t)((size_t)b*Hn + h)*Sn + s)*16 + c] = in[p];
}

// ---------------------------------------------------------------------------
// Causal flash attention, fp32. Q,K,V: [B,H,S,64]. O: [B,S,D] layout.
// 64x64 tiles, 256 threads, 4x4 micro, online softmax w/ shfl row-reduce.
// ---------------------------------------------------------------------------
__global__ __launch_bounds__(256) void attn_kernel(const float* __restrict__ Q,
                                                   const float* __restrict__ K,
                                                   const float* __restrict__ V,
                                                   float* __restrict__ O) {
    extern __shared__ float sm[];
    float* Qs = sm;                 // [64][65]
    float* Ks = sm + 64*65;         // [64][65]
    float* Vs = sm + 2*64*65;       // [64][65]
    float* Ps = sm + 3*64*65;       // [64][65]

    int tid = threadIdx.x;
    int tx = tid & 15, ty = tid >> 4;
    int bh = blockIdx.y;
    int qt = blockIdx.x;
    int qbase = qt * 64;

    const float* Qp = Q + ((size_t)bh*Sn + qbase) * DKn;
#pragma unroll
    for (int e = tid; e < 1024; e += 256) {
        int r = e >> 4, c4 = (e & 15) * 4;
        float4 v = *(const float4*)(Qp + r*64 + c4);
        Qs[r*65 + c4 + 0] = v.x; Qs[r*65 + c4 + 1] = v.y;
        Qs[r*65 + c4 + 2] = v.z; Qs[r*65 + c4 + 3] = v.w;
    }

    float o[4][4];
    float mi[4], li[4];
#pragma unroll
    for (int i = 0; i < 4; i++) {
        mi[i] = -1e30f; li[i] = 0.f;
#pragma unroll
        for (int j = 0; j < 4; j++) o[i][j] = 0.f;
    }

    for (int kt = 0; kt <= qt; kt++) {
        const float* Kp = K + ((size_t)bh*Sn + kt*64) * DKn;
        const float* Vp = V + ((size_t)bh*Sn + kt*64) * DKn;
#pragma unroll
        for (int e = tid; e < 1024; e += 256) {
            int r = e >> 4, c4 = (e & 15) * 4;
            float4 kv = *(const float4*)(Kp + r*64 + c4);
            Ks[r*65 + c4 + 0] = kv.x; Ks[r*65 + c4 + 1] = kv.y;
            Ks[r*65 + c4 + 2] = kv.z; Ks[r*65 + c4 + 3] = kv.w;
            float4 vv = *(const float4*)(Vp + r*64 + c4);
            Vs[r*65 + c4 + 0] = vv.x; Vs[r*65 + c4 + 1] = vv.y;
            Vs[r*65 + c4 + 2] = vv.z; Vs[r*65 + c4 + 3] = vv.w;
        }
        __syncthreads();

        // S = Q K^T  (64x64 tile)
        float sacc[4][4];
#pragma unroll
        for (int i = 0; i < 4; i++)
#pragma unroll
            for (int j = 0; j < 4; j++) sacc[i][j] = 0.f;

#pragma unroll 8
        for (int d = 0; d < 64; d++) {
            float qv[4], kv[4];
#pragma unroll
            for (int i = 0; i < 4; i++) qv[i] = Qs[(ty*4+i)*65 + d];
#pragma unroll
            for (int j = 0; j < 4; j++) kv[j] = Ks[(tx*4+j)*65 + d];
#pragma unroll
            for (int i = 0; i < 4; i++)
#pragma unroll
                for (int j = 0; j < 4; j++)
                    sacc[i][j] = fmaf(qv[i], kv[j], sacc[i][j]);
        }

        const float SCALE = 0.125f;  // 1/sqrt(64)
        bool diag = (kt == qt);

#pragma unroll
        for (int i = 0; i < 4; i++) {
            int qrow = ty*4 + i;
            float rowm = -1e30f;
#pragma unroll
            for (int j = 0; j < 4; j++) {
                float sv = sacc[i][j] * SCALE;
                if (diag && (tx*4 + j) > qrow) sv = -1e30f;
                sacc[i][j] = sv;
                rowm = fmaxf(rowm, sv);
            }
#pragma unroll
            for (int off = 8; off >= 1; off >>= 1)
                rowm = fmaxf(rowm, __shfl_xor_sync(0xffffffffu, rowm, off, 16));
            float mnew = fmaxf(mi[i], rowm);
            float alpha = __expf(mi[i] - mnew);
            float rsum = 0.f;
#pragma unroll
            for (int j = 0; j < 4; j++) {
                float pv = __expf(sacc[i][j] - mnew);
                Ps[(ty*4+i)*65 + tx*4 + j] = pv;
                rsum += pv;
            }
#pragma unroll
            for (int off = 8; off >= 1; off >>= 1)
                rsum += __shfl_xor_sync(0xffffffffu, rsum, off, 16);
            li[i] = li[i] * alpha + rsum;
            mi[i] = mnew;
#pragma unroll
            for (int j = 0; j < 4; j++) o[i][j] *= alpha;
        }
        __syncthreads();

        // O += P V
#pragma unroll 8
        for (int c = 0; c < 64; c++) {
            float pr[4], vv[4];
#pragma unroll
            for (int i = 0; i < 4; i++) pr[i] = Ps[(ty*4+i)*65 + c];
#pragma unroll
            for (int j = 0; j < 4; j++) vv[j] = Vs[c*65 + tx*4 + j];
#pragma unroll
            for (int i = 0; i < 4; i++)
#pragma unroll
                for (int j = 0; j < 4; j++)
                    o[i][j] = fmaf(pr[i], vv[j], o[i][j]);
        }
        __syncthreads();
    }

    int b = bh >> 4, h = bh & 15;
#pragma unroll
    for (int i = 0; i < 4; i++) {
        float inv = 1.f / li[i];
        float* Op = O + ((size_t)((size_t)b*Sn + qbase + ty*4 + i))*Dn + h*DKn + tx*4;
        *(float4*)Op = make_float4(o[i][0]*inv, o[i][1]*inv, o[i][2]*inv, o[i][3]*inv);
    }
}

// ---------------------------------------------------------------------------
extern "C" void kernel_launch(void* const* d_in, const int* in_sizes, int n_in,
                              void* d_out, int out_size) {
    const float* x  = (const float*)d_in[0];
    // d_in[1] = mask (causal tril, implicit in kernel)
    const float* wq = (const float*)d_in[2];
    const float* wk = (const float*)d_in[3];
    const float* wv = (const float*)d_in[4];
    const float* wo = (const float*)d_in[5];
    float* out = (float*)d_out;

    float *q, *k, *v, *t;
    cudaGetSymbolAddress((void**)&q, g_q);
    cudaGetSymbolAddress((void**)&k, g_k);
    cudaGetSymbolAddress((void**)&v, g_v);
    cudaGetSymbolAddress((void**)&t, g_t);

    static bool attr_set = false;
    if (!attr_set) {
        cudaFuncSetAttribute(attn_kernel,
                             cudaFuncAttributeMaxDynamicSharedMemorySize,
                             4*64*65*sizeof(float));
        attr_set = true;
    }

    dim3 gg(Dn/128, Mn/128);           // (8, 64)
    int rope_total = Bn*Sn*Hn*32;      // 4194304
    int vperm_total = Bn*Sn*Hn*16;     // 2097152

    gemm_nt<<<gg, 256>>>(x, wq, t);
    rope_kernel<<<(rope_total + 255)/256, 256>>>(t, q);
    gemm_nt<<<gg, 256>>>(x, wk, t);
    rope_kernel<<<(rope_total + 255)/256, 256>>>(t, k);
    gemm_nt<<<gg, 256>>>(x, wv, t);
    vperm_kernel<<<(vperm_total + 255)/256, 256>>>((const float4*)t, (float4*)v);
    attn_kernel<<<dim3(Sn/64, Bn*Hn), 256, 4*64*65*sizeof(float)>>>(q, k, v, t);
    gemm_nt<<<gg, 256>>>(t, wo, out);
}

// round 2
// speedup vs baseline: 1.4962x; 1.4962x over previous
#include <cuda_runtime.h>
#include <cuda_bf16.h>
#include <math.h>

#define Bn 4
#define Sn 2048
#define Dn 1024
#define Hn 16
#define DKn 64
#define Mn (Bn*Sn)

// Scratch (static device globals: allocation-free)
__device__ float g_q[(size_t)Bn*Hn*Sn*DKn];
__device__ float g_k[(size_t)Bn*Hn*Sn*DKn];
__device__ float g_v[(size_t)Bn*Hn*Sn*DKn];
__device__ float g_t[(size_t)Bn*Sn*Dn];
__device__ __nv_bfloat16 g_ah[(size_t)Mn*Dn];
__device__ __nv_bfloat16 g_al[(size_t)Mn*Dn];
__device__ __nv_bfloat16 g_wh[(size_t)Dn*Dn];
__device__ __nv_bfloat16 g_wl[(size_t)Dn*Dn];

// ---------------------------------------------------------------------------
// Split fp32 -> bf16 hi + bf16 lo (x = hi + lo, lo captures rounding residual)
// ---------------------------------------------------------------------------
__global__ void split_kernel(const float* __restrict__ in,
                             __nv_bfloat16* __restrict__ hi,
                             __nv_bfloat16* __restrict__ lo, int n4) {
    int i = blockIdx.x * blockDim.x + threadIdx.x;
    if (i >= n4) return;
    float4 v = *(const float4*)(in + 4*(size_t)i);
    __nv_bfloat16 h0 = __float2bfloat16(v.x);
    __nv_bfloat16 h1 = __float2bfloat16(v.y);
    __nv_bfloat16 h2 = __float2bfloat16(v.z);
    __nv_bfloat16 h3 = __float2bfloat16(v.w);
    __nv_bfloat16 l0 = __float2bfloat16(v.x - __bfloat162float(h0));
    __nv_bfloat16 l1 = __float2bfloat16(v.y - __bfloat162float(h1));
    __nv_bfloat16 l2 = __float2bfloat16(v.z - __bfloat162float(h2));
    __nv_bfloat16 l3 = __float2bfloat16(v.w - __bfloat162float(h3));
    __nv_bfloat162* ph = (__nv_bfloat162*)(hi + 4*(size_t)i);
    __nv_bfloat162* pl = (__nv_bfloat162*)(lo + 4*(size_t)i);
    ph[0] = __nv_bfloat162(h0, h1); ph[1] = __nv_bfloat162(h2, h3);
    pl[0] = __nv_bfloat162(l0, l1); pl[1] = __nv_bfloat162(l2, l3);
}

// ---------------------------------------------------------------------------
// mma.sync m16n8k16 bf16 (row.col), fp32 accumulate
// ---------------------------------------------------------------------------
__device__ __forceinline__ void mma16816(float* c, const unsigned* a, const unsigned* b) {
    asm volatile(
        "mma.sync.aligned.m16n8k16.row.col.f32.bf16.bf16.f32 "
        "{%0,%1,%2,%3}, {%4,%5,%6,%7}, {%8,%9}, {%0,%1,%2,%3};"
        : "+f"(c[0]), "+f"(c[1]), "+f"(c[2]), "+f"(c[3])
        : "r"(a[0]), "r"(a[1]), "r"(a[2]), "r"(a[3]), "r"(b[0]), "r"(b[1]));
}

// ---------------------------------------------------------------------------
// C[m,n] = sum_k A[m,k]*W[n,k], split-bf16 tensor-core GEMM.
// A,W given as (hi,lo) bf16 pairs; C fp32. 128x128 tile, BK=32, 256 threads.
// Product = Ah*Wh + Ah*Wl + Al*Wh (Al*Wl ~ 2^-18, dropped).
// ---------------------------------------------------------------------------
#define LDP 40   // padded row length in halfs (stride 20 words: conflict-free)
__global__ __launch_bounds__(256, 2) void gemm_mma(
    const __nv_bfloat16* __restrict__ Ah, const __nv_bfloat16* __restrict__ Al,
    const __nv_bfloat16* __restrict__ Wh, const __nv_bfloat16* __restrict__ Wl,
    float* __restrict__ C) {
    __shared__ __nv_bfloat16 As_h[128*LDP], As_l[128*LDP];
    __shared__ __nv_bfloat16 Bs_h[128*LDP], Bs_l[128*LDP];

    int tid = threadIdx.x;
    int wid = tid >> 5, lane = tid & 31;
    int grp = lane >> 2, t4 = lane & 3;
    int wm = (wid >> 2) * 64;   // warp m-offset within tile (0 or 64)
    int wn = (wid & 3) * 32;    // warp n-offset within tile
    int mbase = blockIdx.y * 128, nbase = blockIdx.x * 128;

    int lr = tid >> 2;          // 0..63 (loader row)
    int lq = (tid & 3) * 8;     // loader half-offset within row

    float acc[4][4][4];
#pragma unroll
    for (int mi = 0; mi < 4; mi++)
#pragma unroll
        for (int ni = 0; ni < 4; ni++)
#pragma unroll
            for (int e = 0; e < 4; e++) acc[mi][ni][e] = 0.f;

    for (int k0 = 0; k0 < Dn; k0 += 32) {
#pragma unroll
        for (int rr = 0; rr < 2; rr++) {
            int row = lr + rr * 64;
            size_t goff = (size_t)(mbase + row) * Dn + k0 + lq;
            size_t woff = (size_t)(nbase + row) * Dn + k0 + lq;
            uint4 vah = *(const uint4*)(Ah + goff);
            uint4 val = *(const uint4*)(Al + goff);
            uint4 vwh = *(const uint4*)(Wh + woff);
            uint4 vwl = *(const uint4*)(Wl + woff);
            *(uint4*)&As_h[row*LDP + lq] = vah;
            *(uint4*)&As_l[row*LDP + lq] = val;
            *(uint4*)&Bs_h[row*LDP + lq] = vwh;
            *(uint4*)&Bs_l[row*LDP + lq] = vwl;
        }
        __syncthreads();

#pragma unroll
        for (int kk = 0; kk < 32; kk += 16) {
            unsigned afh[4][4], afl[4][4];
#pragma unroll
            for (int mi = 0; mi < 4; mi++) {
                int ar = wm + mi*16 + grp;
                int base = ar*LDP + kk + t4*2;
                afh[mi][0] = *(const unsigned*)&As_h[base];
                afh[mi][1] = *(const unsigned*)&As_h[base + 8*LDP];
                afh[mi][2] = *(const unsigned*)&As_h[base + 8];
                afh[mi][3] = *(const unsigned*)&As_h[base + 8*LDP + 8];
                afl[mi][0] = *(const unsigned*)&As_l[base];
                afl[mi][1] = *(const unsigned*)&As_l[base + 8*LDP];
                afl[mi][2] = *(const unsigned*)&As_l[base + 8];
                afl[mi][3] = *(const unsigned*)&As_l[base + 8*LDP + 8];
            }
#pragma unroll
            for (int ni = 0; ni < 4; ni++) {
                int br = wn + ni*8 + grp;
                int bb = br*LDP + kk + t4*2;
                unsigned bfh[2], bfl[2];
                bfh[0] = *(const unsigned*)&Bs_h[bb];
                bfh[1] = *(const unsigned*)&Bs_h[bb + 8];
                bfl[0] = *(const unsigned*)&Bs_l[bb];
                bfl[1] = *(const unsigned*)&Bs_l[bb + 8];
#pragma unroll
                for (int mi = 0; mi < 4; mi++) {
                    mma16816(acc[mi][ni], afh[mi], bfh);
                    mma16816(acc[mi][ni], afh[mi], bfl);
                    mma16816(acc[mi][ni], afl[mi], bfh);
                }
            }
        }
        __syncthreads();
    }

#pragma unroll
    for (int mi = 0; mi < 4; mi++) {
#pragma unroll
        for (int ni = 0; ni < 4; ni++) {
            int row0 = mbase + wm + mi*16 + grp;
            int col  = nbase + wn + ni*8 + t4*2;
            float2* p0 = (float2*)(C + (size_t)row0 * Dn + col);
            float2* p1 = (float2*)(C + (size_t)(row0 + 8) * Dn + col);
            *p0 = make_float2(acc[mi][ni][0], acc[mi][ni][1]);
            *p1 = make_float2(acc[mi][ni][2], acc[mi][ni][3]);
        }
    }
}

// ---------------------------------------------------------------------------
// RoPE + head transpose: in [B,S,H,DK] -> out [B,H,S,DK]
// ---------------------------------------------------------------------------
__global__ void rope_kernel(const float* __restrict__ in, float* __restrict__ out) {
    int p = blockIdx.x * blockDim.x + threadIdx.x;
    if (p >= Bn*Sn*Hn*32) return;
    int i = p & 31;
    int h = (p >> 5) & (Hn-1);
    int s = (p >> 9) & (Sn-1);
    int b = p >> 20;
    const float* src = in + ((size_t)((size_t)b*Sn + s)*Hn + h)*DKn + 2*i;
    float x1 = src[0], x2 = src[1];
    float freq = expf(-((float)(2*i) / (float)DKn) * 9.210340371976184f);
    float ang = (float)s * freq;
    float sn, cs;
    sincosf(ang, &sn, &cs);
    float* dst = out + ((size_t)((size_t)b*Hn + h)*Sn + s)*DKn + 2*i;
    dst[0] = x1*cs - x2*sn;
    dst[1] = x1*sn + x2*cs;
}

__global__ void vperm_kernel(const float4* __restrict__ in, float4* __restrict__ out) {
    int p = blockIdx.x * blockDim.x + threadIdx.x;
    if (p >= Bn*Sn*Hn*16) return;
    int c = p & 15;
    int h = (p >> 4) & 15;
    int s = (p >> 8) & 2047;
    int b = p >> 19;
    out[((size_t)((size_t)b*Hn + h)*Sn + s)*16 + c] = in[p];
}

// ---------------------------------------------------------------------------
// Causal flash attention, fp32 SIMT (round-2 target for tensorization).
// ---------------------------------------------------------------------------
__global__ __launch_bounds__(256) void attn_kernel(const float* __restrict__ Q,
                                                   const float* __restrict__ K,
                                                   const float* __restrict__ V,
                                                   float* __restrict__ O) {
    extern __shared__ float sm[];
    float* Qs = sm;
    float* Ks = sm + 64*65;
    float* Vs = sm + 2*64*65;
    float* Ps = sm + 3*64*65;

    int tid = threadIdx.x;
    int tx = tid & 15, ty = tid >> 4;
    int bh = blockIdx.y;
    int qt = blockIdx.x;
    int qbase = qt * 64;

    const float* Qp = Q + ((size_t)bh*Sn + qbase) * DKn;
#pragma unroll
    for (int e = tid; e < 1024; e += 256) {
        int r = e >> 4, c4 = (e & 15) * 4;
        float4 v = *(const float4*)(Qp + r*64 + c4);
        Qs[r*65 + c4 + 0] = v.x; Qs[r*65 + c4 + 1] = v.y;
        Qs[r*65 + c4 + 2] = v.z; Qs[r*65 + c4 + 3] = v.w;
    }

    float o[4][4];
    float mi[4], li[4];
#pragma unroll
    for (int i = 0; i < 4; i++) {
        mi[i] = -1e30f; li[i] = 0.f;
#pragma unroll
        for (int j = 0; j < 4; j++) o[i][j] = 0.f;
    }

    for (int kt = 0; kt <= qt; kt++) {
        const float* Kp = K + ((size_t)bh*Sn + kt*64) * DKn;
        const float* Vp = V + ((size_t)bh*Sn + kt*64) * DKn;
#pragma unroll
        for (int e = tid; e < 1024; e += 256) {
            int r = e >> 4, c4 = (e & 15) * 4;
            float4 kv = *(const float4*)(Kp + r*64 + c4);
            Ks[r*65 + c4 + 0] = kv.x; Ks[r*65 + c4 + 1] = kv.y;
            Ks[r*65 + c4 + 2] = kv.z; Ks[r*65 + c4 + 3] = kv.w;
            float4 vv = *(const float4*)(Vp + r*64 + c4);
            Vs[r*65 + c4 + 0] = vv.x; Vs[r*65 + c4 + 1] = vv.y;
            Vs[r*65 + c4 + 2] = vv.z; Vs[r*65 + c4 + 3] = vv.w;
        }
        __syncthreads();

        float sacc[4][4];
#pragma unroll
        for (int i = 0; i < 4; i++)
#pragma unroll
            for (int j = 0; j < 4; j++) sacc[i][j] = 0.f;

#pragma unroll 8
        for (int d = 0; d < 64; d++) {
            float qv[4], kv[4];
#pragma unroll
            for (int i = 0; i < 4; i++) qv[i] = Qs[(ty*4+i)*65 + d];
#pragma unroll
            for (int j = 0; j < 4; j++) kv[j] = Ks[(tx*4+j)*65 + d];
#pragma unroll
            for (int i = 0; i < 4; i++)
#pragma unroll
                for (int j = 0; j < 4; j++)
                    sacc[i][j] = fmaf(qv[i], kv[j], sacc[i][j]);
        }

        const float SCALE = 0.125f;
        bool diag = (kt == qt);

#pragma unroll
        for (int i = 0; i < 4; i++) {
            int qrow = ty*4 + i;
            float rowm = -1e30f;
#pragma unroll
            for (int j = 0; j < 4; j++) {
                float sv = sacc[i][j] * SCALE;
                if (diag && (tx*4 + j) > qrow) sv = -1e30f;
                sacc[i][j] = sv;
                rowm = fmaxf(rowm, sv);
            }
#pragma unroll
            for (int off = 8; off >= 1; off >>= 1)
                rowm = fmaxf(rowm, __shfl_xor_sync(0xffffffffu, rowm, off, 16));
            float mnew = fmaxf(mi[i], rowm);
            float alpha = __expf(mi[i] - mnew);
            float rsum = 0.f;
#pragma unroll
            for (int j = 0; j < 4; j++) {
                float pv = __expf(sacc[i][j] - mnew);
                Ps[(ty*4+i)*65 + tx*4 + j] = pv;
                rsum += pv;
            }
#pragma unroll
            for (int off = 8; off >= 1; off >>= 1)
                rsum += __shfl_xor_sync(0xffffffffu, rsum, off, 16);
            li[i] = li[i] * alpha + rsum;
            mi[i] = mnew;
#pragma unroll
            for (int j = 0; j < 4; j++) o[i][j] *= alpha;
        }
        __syncthreads();

#pragma unroll 8
        for (int c = 0; c < 64; c++) {
            float pr[4], vv[4];
#pragma unroll
            for (int i = 0; i < 4; i++) pr[i] = Ps[(ty*4+i)*65 + c];
#pragma unroll
            for (int j = 0; j < 4; j++) vv[j] = Vs[c*65 + tx*4 + j];
#pragma unroll
            for (int i = 0; i < 4; i++)
#pragma unroll
                for (int j = 0; j < 4; j++)
                    o[i][j] = fmaf(pr[i], vv[j], o[i][j]);
        }
        __syncthreads();
    }

    int b = bh >> 4, h = bh & 15;
#pragma unroll
    for (int i = 0; i < 4; i++) {
        float inv = 1.f / li[i];
        float* Op = O + ((size_t)((size_t)b*Sn + qbase + ty*4 + i))*Dn + h*DKn + tx*4;
        *(float4*)Op = make_float4(o[i][0]*inv, o[i][1]*inv, o[i][2]*inv, o[i][3]*inv);
    }
}

// ---------------------------------------------------------------------------
extern "C" void kernel_launch(void* const* d_in, const int* in_sizes, int n_in,
                              void* d_out, int out_size) {
    const float* x  = (const float*)d_in[0];
    const float* wq = (const float*)d_in[2];
    const float* wk = (const float*)d_in[3];
    const float* wv = (const float*)d_in[4];
    const float* wo = (const float*)d_in[5];
    float* out = (float*)d_out;

    float *q, *k, *v, *t;
    __nv_bfloat16 *ah, *al, *wh, *wl;
    cudaGetSymbolAddress((void**)&q, g_q);
    cudaGetSymbolAddress((void**)&k, g_k);
    cudaGetSymbolAddress((void**)&v, g_v);
    cudaGetSymbolAddress((void**)&t, g_t);
    cudaGetSymbolAddress((void**)&ah, g_ah);
    cudaGetSymbolAddress((void**)&al, g_al);
    cudaGetSymbolAddress((void**)&wh, g_wh);
    cudaGetSymbolAddress((void**)&wl, g_wl);

    static bool attr_set = false;
    if (!attr_set) {
        cudaFuncSetAttribute(attn_kernel,
                             cudaFuncAttributeMaxDynamicSharedMemorySize,
                             4*64*65*sizeof(float));
        attr_set = true;
    }

    dim3 gg(Dn/128, Mn/128);           // (8, 64)
    int xn4 = Mn*Dn/4, wn4 = Dn*Dn/4;
    int rope_total = Bn*Sn*Hn*32;
    int vperm_total = Bn*Sn*Hn*16;

    split_kernel<<<(xn4 + 255)/256, 256>>>(x, ah, al, xn4);

    split_kernel<<<(wn4 + 255)/256, 256>>>(wq, wh, wl, wn4);
    gemm_mma<<<gg, 256>>>(ah, al, wh, wl, t);
    rope_kernel<<<(rope_total + 255)/256, 256>>>(t, q);

    split_kernel<<<(wn4 + 255)/256, 256>>>(wk, wh, wl, wn4);
    gemm_mma<<<gg, 256>>>(ah, al, wh, wl, t);
    rope_kernel<<<(rope_total + 255)/256, 256>>>(t, k);

    split_kernel<<<(wn4 + 255)/256, 256>>>(wv, wh, wl, wn4);
    gemm_mma<<<gg, 256>>>(ah, al, wh, wl, t);
    vperm_kernel<<<(vperm_total + 255)/256, 256>>>((const float4*)t, (float4*)v);

    attn_kernel<<<dim3(Sn/64, Bn*Hn), 256, 4*64*65*sizeof(float)>>>(q, k, v, t);

    split_kernel<<<(xn4 + 255)/256, 256>>>(t, ah, al, xn4);
    split_kernel<<<(wn4 + 255)/256, 256>>>(wo, wh, wl, wn4);
    gemm_mma<<<gg, 256>>>(ah, al, wh, wl, out);
}

// round 3
// speedup vs baseline: 2.3926x; 1.5991x over previous
#include <cuda_runtime.h>
#include <cuda_bf16.h>
#include <math.h>

#define Bn 4
#define Sn 2048
#define Dn 1024
#define Hn 16
#define DKn 64
#define Mn (Bn*Sn)

// Scratch (static device globals: allocation-free)
__device__ float g_t[(size_t)Bn*Sn*Dn];
__device__ __nv_bfloat16 g_ah[(size_t)Mn*Dn];
__device__ __nv_bfloat16 g_al[(size_t)Mn*Dn];
__device__ __nv_bfloat16 g_wh[(size_t)Dn*Dn];
__device__ __nv_bfloat16 g_wl[(size_t)Dn*Dn];
__device__ __nv_bfloat16 g_qh[(size_t)Bn*Hn*Sn*DKn];
__device__ __nv_bfloat16 g_ql[(size_t)Bn*Hn*Sn*DKn];
__device__ __nv_bfloat16 g_kh[(size_t)Bn*Hn*Sn*DKn];
__device__ __nv_bfloat16 g_kl[(size_t)Bn*Hn*Sn*DKn];
__device__ __nv_bfloat16 g_vh[(size_t)Bn*Hn*Sn*DKn];   // [bh][dk][s] transposed
__device__ __nv_bfloat16 g_vl[(size_t)Bn*Hn*Sn*DKn];

// ---------------------------------------------------------------------------
__global__ void split_kernel(const float* __restrict__ in,
                             __nv_bfloat16* __restrict__ hi,
                             __nv_bfloat16* __restrict__ lo, int n4) {
    int i = blockIdx.x * blockDim.x + threadIdx.x;
    if (i >= n4) return;
    float4 v = *(const float4*)(in + 4*(size_t)i);
    __nv_bfloat16 h0 = __float2bfloat16(v.x);
    __nv_bfloat16 h1 = __float2bfloat16(v.y);
    __nv_bfloat16 h2 = __float2bfloat16(v.z);
    __nv_bfloat16 h3 = __float2bfloat16(v.w);
    __nv_bfloat16 l0 = __float2bfloat16(v.x - __bfloat162float(h0));
    __nv_bfloat16 l1 = __float2bfloat16(v.y - __bfloat162float(h1));
    __nv_bfloat16 l2 = __float2bfloat16(v.z - __bfloat162float(h2));
    __nv_bfloat16 l3 = __float2bfloat16(v.w - __bfloat162float(h3));
    __nv_bfloat162* ph = (__nv_bfloat162*)(hi + 4*(size_t)i);
    __nv_bfloat162* pl = (__nv_bfloat162*)(lo + 4*(size_t)i);
    ph[0] = __nv_bfloat162(h0, h1); ph[1] = __nv_bfloat162(h2, h3);
    pl[0] = __nv_bfloat162(l0, l1); pl[1] = __nv_bfloat162(l2, l3);
}

// ---------------------------------------------------------------------------
__device__ __forceinline__ void mma16816(float* c, const unsigned* a, const unsigned* b) {
    asm volatile(
        "mma.sync.aligned.m16n8k16.row.col.f32.bf16.bf16.f32 "
        "{%0,%1,%2,%3}, {%4,%5,%6,%7}, {%8,%9}, {%0,%1,%2,%3};"
        : "+f"(c[0]), "+f"(c[1]), "+f"(c[2]), "+f"(c[3])
        : "r"(a[0]), "r"(a[1]), "r"(a[2]), "r"(a[3]), "r"(b[0]), "r"(b[1]));
}

__device__ __forceinline__ unsigned pack2(float x, float y) {
    __nv_bfloat162 t = __floats2bfloat162_rn(x, y);
    return *(unsigned*)&t;
}

// ---------------------------------------------------------------------------
// Split-bf16 tensor-core GEMM. C[m,n] = sum_k A[m,k]*W[n,k].
// 128x128 tile, BK=32, 256 threads.
// ---------------------------------------------------------------------------
#define LDP 40
__global__ __launch_bounds__(256, 2) void gemm_mma(
    const __nv_bfloat16* __restrict__ Ah, const __nv_bfloat16* __restrict__ Al,
    const __nv_bfloat16* __restrict__ Wh, const __nv_bfloat16* __restrict__ Wl,
    float* __restrict__ C) {
    __shared__ __nv_bfloat16 As_h[128*LDP], As_l[128*LDP];
    __shared__ __nv_bfloat16 Bs_h[128*LDP], Bs_l[128*LDP];

    int tid = threadIdx.x;
    int wid = tid >> 5, lane = tid & 31;
    int grp = lane >> 2, t4 = lane & 3;
    int wm = (wid >> 2) * 64;
    int wn = (wid & 3) * 32;
    int mbase = blockIdx.y * 128, nbase = blockIdx.x * 128;

    int lr = tid >> 2;
    int lq = (tid & 3) * 8;

    float acc[4][4][4];
#pragma unroll
    for (int mi = 0; mi < 4; mi++)
#pragma unroll
        for (int ni = 0; ni < 4; ni++)
#pragma unroll
            for (int e = 0; e < 4; e++) acc[mi][ni][e] = 0.f;

    for (int k0 = 0; k0 < Dn; k0 += 32) {
#pragma unroll
        for (int rr = 0; rr < 2; rr++) {
            int row = lr + rr * 64;
            size_t goff = (size_t)(mbase + row) * Dn + k0 + lq;
            size_t woff = (size_t)(nbase + row) * Dn + k0 + lq;
            uint4 vah = *(const uint4*)(Ah + goff);
            uint4 val = *(const uint4*)(Al + goff);
            uint4 vwh = *(const uint4*)(Wh + woff);
            uint4 vwl = *(const uint4*)(Wl + woff);
            *(uint4*)&As_h[row*LDP + lq] = vah;
            *(uint4*)&As_l[row*LDP + lq] = val;
            *(uint4*)&Bs_h[row*LDP + lq] = vwh;
            *(uint4*)&Bs_l[row*LDP + lq] = vwl;
        }
        __syncthreads();

#pragma unroll
        for (int kk = 0; kk < 32; kk += 16) {
            unsigned afh[4][4], afl[4][4];
#pragma unroll
            for (int mi = 0; mi < 4; mi++) {
                int ar = wm + mi*16 + grp;
                int base = ar*LDP + kk + t4*2;
                afh[mi][0] = *(const unsigned*)&As_h[base];
                afh[mi][1] = *(const unsigned*)&As_h[base + 8*LDP];
                afh[mi][2] = *(const unsigned*)&As_h[base + 8];
                afh[mi][3] = *(const unsigned*)&As_h[base + 8*LDP + 8];
                afl[mi][0] = *(const unsigned*)&As_l[base];
                afl[mi][1] = *(const unsigned*)&As_l[base + 8*LDP];
                afl[mi][2] = *(const unsigned*)&As_l[base + 8];
                afl[mi][3] = *(const unsigned*)&As_l[base + 8*LDP + 8];
            }
#pragma unroll
            for (int ni = 0; ni < 4; ni++) {
                int br = wn + ni*8 + grp;
                int bb = br*LDP + kk + t4*2;
                unsigned bfh[2], bfl[2];
                bfh[0] = *(const unsigned*)&Bs_h[bb];
                bfh[1] = *(const unsigned*)&Bs_h[bb + 8];
                bfl[0] = *(const unsigned*)&Bs_l[bb];
                bfl[1] = *(const unsigned*)&Bs_l[bb + 8];
#pragma unroll
                for (int mi = 0; mi < 4; mi++) {
                    mma16816(acc[mi][ni], afh[mi], bfh);
                    mma16816(acc[mi][ni], afh[mi], bfl);
                    mma16816(acc[mi][ni], afl[mi], bfh);
                }
            }
        }
        __syncthreads();
    }

#pragma unroll
    for (int mi = 0; mi < 4; mi++) {
#pragma unroll
        for (int ni = 0; ni < 4; ni++) {
            int row0 = mbase + wm + mi*16 + grp;
            int col  = nbase + wn + ni*8 + t4*2;
            float2* p0 = (float2*)(C + (size_t)row0 * Dn + col);
            float2* p1 = (float2*)(C + (size_t)(row0 + 8) * Dn + col);
            *p0 = make_float2(acc[mi][ni][0], acc[mi][ni][1]);
            *p1 = make_float2(acc[mi][ni][2], acc[mi][ni][3]);
        }
    }
}

// ---------------------------------------------------------------------------
// RoPE + head transpose + bf16 split: [B,S,H,DK] fp32 -> [B,H,S,DK] bf16 hi/lo
// ---------------------------------------------------------------------------
__global__ void rope_kernel(const float* __restrict__ in,
                            __nv_bfloat16* __restrict__ outh,
                            __nv_bfloat16* __restrict__ outl) {
    int p = blockIdx.x * blockDim.x + threadIdx.x;
    if (p >= Bn*Sn*Hn*32) return;
    int i = p & 31;
    int h = (p >> 5) & (Hn-1);
    int s = (p >> 9) & (Sn-1);
    int b = p >> 20;
    const float* src = in + ((size_t)((size_t)b*Sn + s)*Hn + h)*DKn + 2*i;
    float x1 = src[0], x2 = src[1];
    float freq = expf(-((float)(2*i) / (float)DKn) * 9.210340371976184f);
    float ang = (float)s * freq;
    float sn, cs;
    sincosf(ang, &sn, &cs);
    float r0 = x1*cs - x2*sn;
    float r1 = x1*sn + x2*cs;
    __nv_bfloat16 h0 = __float2bfloat16(r0);
    __nv_bfloat16 h1 = __float2bfloat16(r1);
    __nv_bfloat16 l0 = __float2bfloat16(r0 - __bfloat162float(h0));
    __nv_bfloat16 l1 = __float2bfloat16(r1 - __bfloat162float(h1));
    size_t doff = ((size_t)((size_t)b*Hn + h)*Sn + s)*DKn + 2*i;
    *(__nv_bfloat162*)(outh + doff) = __nv_bfloat162(h0, h1);
    *(__nv_bfloat162*)(outl + doff) = __nv_bfloat162(l0, l1);
}

// ---------------------------------------------------------------------------
// V: [B,S,H,DK] fp32 -> transposed split bf16 [bh][dk=64][S]
// Block: one bh, 64-seq tile. 256 threads.
// ---------------------------------------------------------------------------
__global__ __launch_bounds__(256) void vsplit_kernel(const float* __restrict__ t,
                                                     __nv_bfloat16* __restrict__ Vh,
                                                     __nv_bfloat16* __restrict__ Vl) {
    __shared__ __nv_bfloat16 sh[64*72], sl[64*72];
    int tid = threadIdx.x;
    int bh = blockIdx.y;
    int b = bh >> 4, h = bh & 15;
    int s0 = blockIdx.x * 64;

    int r = tid >> 2;            // seq row within tile 0..63
    int c0 = (tid & 3) * 16;     // dk offset 0..48
    const float* src = t + ((size_t)((size_t)b*Sn + s0 + r)*Hn + h)*DKn + c0;
#pragma unroll
    for (int i = 0; i < 4; i++) {
        float4 v = *(const float4*)(src + i*4);
        float vv[4] = {v.x, v.y, v.z, v.w};
#pragma unroll
        for (int j = 0; j < 4; j++) {
            int d = c0 + i*4 + j;
            __nv_bfloat16 hh = __float2bfloat16(vv[j]);
            sh[d*72 + r] = hh;
            sl[d*72 + r] = __float2bfloat16(vv[j] - __bfloat162float(hh));
        }
    }
    __syncthreads();

    int d = tid >> 2;            // dk row 0..63
    int k0 = (tid & 3) * 16;     // seq offset within tile
    size_t doff = ((size_t)bh*64 + d)*Sn + s0 + k0;
    *(uint4*)(Vh + doff)     = *(const uint4*)&sh[d*72 + k0];
    *(uint4*)(Vh + doff + 8) = *(const uint4*)&sh[d*72 + k0 + 8];
    *(uint4*)(Vl + doff)     = *(const uint4*)&sl[d*72 + k0];
    *(uint4*)(Vl + doff + 8) = *(const uint4*)&sl[d*72 + k0 + 8];
}

// ---------------------------------------------------------------------------
// Causal flash attention, split-bf16 MMA. Q,K: [bh][s][64]; V: [bh][dk][s].
// Block: 128 q rows (8 warps x 16), K-tiles of 64. Out: fp32 [B,S,D].
// ---------------------------------------------------------------------------
#define LDA 72
__global__ __launch_bounds__(256) void attn_mma(
    const __nv_bfloat16* __restrict__ Qh, const __nv_bfloat16* __restrict__ Ql,
    const __nv_bfloat16* __restrict__ Kh, const __nv_bfloat16* __restrict__ Kl,
    const __nv_bfloat16* __restrict__ Vh, const __nv_bfloat16* __restrict__ Vl,
    float* __restrict__ O) {
    __shared__ __nv_bfloat16 sKh[64*LDA], sKl[64*LDA], sVh[64*LDA], sVl[64*LDA];

    int tid = threadIdx.x;
    int wid = tid >> 5, lane = tid & 31;
    int grp = lane >> 2, t4 = lane & 3;
    int bh = blockIdx.y;
    int qt = blockIdx.x;
    int qbase = qt * 128;
    int lr = tid >> 3;            // loader row 0..31
    int lc = (tid & 7) * 8;       // loader col (halfs)

    // ---- Stage Q fragments into registers (two rounds through K smem) ----
    unsigned qfh[4][4], qfl[4][4];
#pragma unroll
    for (int half = 0; half < 2; half++) {
        const __nv_bfloat16* qsh = Qh + ((size_t)bh*Sn + qbase + half*64)*DKn;
        const __nv_bfloat16* qsl = Ql + ((size_t)bh*Sn + qbase + half*64)*DKn;
#pragma unroll
        for (int rr = 0; rr < 2; rr++) {
            int row = lr + rr*32;
            *(uint4*)&sKh[row*LDA + lc] = *(const uint4*)(qsh + row*DKn + lc);
            *(uint4*)&sKl[row*LDA + lc] = *(const uint4*)(qsl + row*DKn + lc);
        }
        __syncthreads();
        if ((wid >> 2) == half) {
            int r = (wid & 3)*16 + grp;
#pragma unroll
            for (int k4 = 0; k4 < 4; k4++) {
                int kk = k4*16;
                qfh[k4][0] = *(const unsigned*)&sKh[r*LDA + kk + t4*2];
                qfh[k4][1] = *(const unsigned*)&sKh[(r+8)*LDA + kk + t4*2];
                qfh[k4][2] = *(const unsigned*)&sKh[r*LDA + kk + 8 + t4*2];
                qfh[k4][3] = *(const unsigned*)&sKh[(r+8)*LDA + kk + 8 + t4*2];
                qfl[k4][0] = *(const unsigned*)&sKl[r*LDA + kk + t4*2];
                qfl[k4][1] = *(const unsigned*)&sKl[(r+8)*LDA + kk + t4*2];
                qfl[k4][2] = *(const unsigned*)&sKl[r*LDA + kk + 8 + t4*2];
                qfl[k4][3] = *(const unsigned*)&sKl[(r+8)*LDA + kk + 8 + t4*2];
            }
        }
        __syncthreads();
    }

    int row0 = qbase + wid*16 + grp;
    int row1 = row0 + 8;
    float o[8][4];
    float m0 = -1e30f, m1 = -1e30f, l0 = 0.f, l1 = 0.f;
#pragma unroll
    for (int nt = 0; nt < 8; nt++)
#pragma unroll
        for (int e = 0; e < 4; e++) o[nt][e] = 0.f;

    const float SCALE = 0.125f;
    int ktmax = 2*qt + 2;

    for (int kt = 0; kt < ktmax; kt++) {
        int kbase = kt * 64;
        const __nv_bfloat16* ksh = Kh + ((size_t)bh*Sn + kbase)*DKn;
        const __nv_bfloat16* ksl = Kl + ((size_t)bh*Sn + kbase)*DKn;
#pragma unroll
        for (int rr = 0; rr < 2; rr++) {
            int row = lr + rr*32;
            *(uint4*)&sKh[row*LDA + lc] = *(const uint4*)(ksh + row*DKn + lc);
            *(uint4*)&sKl[row*LDA + lc] = *(const uint4*)(ksl + row*DKn + lc);
            size_t voff = ((size_t)bh*64 + row)*Sn + kbase + lc;
            *(uint4*)&sVh[row*LDA + lc] = *(const uint4*)(Vh + voff);
            *(uint4*)&sVl[row*LDA + lc] = *(const uint4*)(Vl + voff);
        }
        __syncthreads();

        // ---- S = Q K^T ----
        float sacc[8][4];
#pragma unroll
        for (int nt = 0; nt < 8; nt++)
#pragma unroll
            for (int e = 0; e < 4; e++) sacc[nt][e] = 0.f;

#pragma unroll
        for (int k4 = 0; k4 < 4; k4++) {
            int kk = k4*16;
#pragma unroll
            for (int nt = 0; nt < 8; nt++) {
                int bb = (nt*8 + grp)*LDA + kk + t4*2;
                unsigned bfh[2], bfl[2];
                bfh[0] = *(const unsigned*)&sKh[bb];
                bfh[1] = *(const unsigned*)&sKh[bb + 8];
                bfl[0] = *(const unsigned*)&sKl[bb];
                bfl[1] = *(const unsigned*)&sKl[bb + 8];
                mma16816(sacc[nt], qfh[k4], bfh);
                mma16816(sacc[nt], qfh[k4], bfl);
                mma16816(sacc[nt], qfl[k4], bfh);
            }
        }

        // ---- masked online softmax ----
        bool diag = (kbase + 64 > qbase + wid*16);
        float rm0 = -1e30f, rm1 = -1e30f;
#pragma unroll
        for (int nt = 0; nt < 8; nt++) {
            int key = kbase + nt*8 + t4*2;
            float s0 = sacc[nt][0]*SCALE, s1 = sacc[nt][1]*SCALE;
            float s2 = sacc[nt][2]*SCALE, s3 = sacc[nt][3]*SCALE;
            if (diag) {
                if (key     > row0) s0 = -1e30f;
                if (key + 1 > row0) s1 = -1e30f;
                if (key     > row1) s2 = -1e30f;
                if (key + 1 > row1) s3 = -1e30f;
            }
            sacc[nt][0] = s0; sacc[nt][1] = s1;
            sacc[nt][2] = s2; sacc[nt][3] = s3;
            rm0 = fmaxf(rm0, fmaxf(s0, s1));
            rm1 = fmaxf(rm1, fmaxf(s2, s3));
        }
        rm0 = fmaxf(rm0, __shfl_xor_sync(0xffffffffu, rm0, 1, 4));
        rm0 = fmaxf(rm0, __shfl_xor_sync(0xffffffffu, rm0, 2, 4));
        rm1 = fmaxf(rm1, __shfl_xor_sync(0xffffffffu, rm1, 1, 4));
        rm1 = fmaxf(rm1, __shfl_xor_sync(0xffffffffu, rm1, 2, 4));

        float mn0 = fmaxf(m0, rm0), mn1 = fmaxf(m1, rm1);
        float a0 = __expf(m0 - mn0), a1 = __expf(m1 - mn1);
        m0 = mn0; m1 = mn1;
        float rs0 = 0.f, rs1 = 0.f;
#pragma unroll
        for (int nt = 0; nt < 8; nt++) {
            float p0 = __expf(sacc[nt][0] - mn0);
            float p1 = __expf(sacc[nt][1] - mn0);
            float p2 = __expf(sacc[nt][2] - mn1);
            float p3 = __expf(sacc[nt][3] - mn1);
            sacc[nt][0] = p0; sacc[nt][1] = p1;
            sacc[nt][2] = p2; sacc[nt][3] = p3;
            rs0 += p0 + p1; rs1 += p2 + p3;
        }
        rs0 += __shfl_xor_sync(0xffffffffu, rs0, 1, 4);
        rs0 += __shfl_xor_sync(0xffffffffu, rs0, 2, 4);
        rs1 += __shfl_xor_sync(0xffffffffu, rs1, 1, 4);
        rs1 += __shfl_xor_sync(0xffffffffu, rs1, 2, 4);
        l0 = l0*a0 + rs0; l1 = l1*a1 + rs1;
#pragma unroll
        for (int nt = 0; nt < 8; nt++) {
            o[nt][0] *= a0; o[nt][1] *= a0;
            o[nt][2] *= a1; o[nt][3] *= a1;
        }

        // ---- O += P V (P frags chained from S accumulators) ----
#pragma unroll
        for (int k4 = 0; k4 < 4; k4++) {
            unsigned pah[4], pal[4];
            float* c0 = sacc[2*k4];
            float* c1 = sacc[2*k4 + 1];
            pah[0] = pack2(c0[0], c0[1]);
            pah[1] = pack2(c0[2], c0[3]);
            pah[2] = pack2(c1[0], c1[1]);
            pah[3] = pack2(c1[2], c1[3]);
            {
                __nv_bfloat162 t0 = *(__nv_bfloat162*)&pah[0];
                __nv_bfloat162 t1 = *(__nv_bfloat162*)&pah[1];
                __nv_bfloat162 t2 = *(__nv_bfloat162*)&pah[2];
                __nv_bfloat162 t3 = *(__nv_bfloat162*)&pah[3];
                pal[0] = pack2(c0[0]-__low2float(t0), c0[1]-__high2float(t0));
                pal[1] = pack2(c0[2]-__low2float(t1), c0[3]-__high2float(t1));
                pal[2] = pack2(c1[0]-__low2float(t2), c1[1]-__high2float(t2));
                pal[3] = pack2(c1[2]-__low2float(t3), c1[3]-__high2float(t3));
            }
            int kk = k4*16;
#pragma unroll
            for (int nt = 0; nt < 8; nt++) {
                int bb = (nt*8 + grp)*LDA + kk + t4*2;
                unsigned vbh[2], vbl[2];
                vbh[0] = *(const unsigned*)&sVh[bb];
                vbh[1] = *(const unsigned*)&sVh[bb + 8];
                vbl[0] = *(const unsigned*)&sVl[bb];
                vbl[1] = *(const unsigned*)&sVl[bb + 8];
                mma16816(o[nt], pah, vbh);
                mma16816(o[nt], pah, vbl);
                mma16816(o[nt], pal, vbh);
            }
        }
        __syncthreads();
    }

    // ---- write O / l into [B,S,D] ----
    int b = bh >> 4, h = bh & 15;
    float inv0 = 1.f / l0, inv1 = 1.f / l1;
#pragma unroll
    for (int nt = 0; nt < 8; nt++) {
        int col = h*DKn + nt*8 + t4*2;
        float2* p0 = (float2*)(O + ((size_t)b*Sn + row0)*Dn + col);
        float2* p1 = (float2*)(O + ((size_t)b*Sn + row1)*Dn + col);
        *p0 = make_float2(o[nt][0]*inv0, o[nt][1]*inv0);
        *p1 = make_float2(o[nt][2]*inv1, o[nt][3]*inv1);
    }
}

// ---------------------------------------------------------------------------
extern "C" void kernel_launch(void* const* d_in, const int* in_sizes, int n_in,
                              void* d_out, int out_size) {
    const float* x  = (const float*)d_in[0];
    const float* wq = (const float*)d_in[2];
    const float* wk = (const float*)d_in[3];
    const float* wv = (const float*)d_in[4];
    const float* wo = (const float*)d_in[5];
    float* out = (float*)d_out;

    float *t;
    __nv_bfloat16 *ah, *al, *wh, *wl, *qh, *ql, *kh, *kl, *vh, *vl;
    cudaGetSymbolAddress((void**)&t,  g_t);
    cudaGetSymbolAddress((void**)&ah, g_ah);
    cudaGetSymbolAddress((void**)&al, g_al);
    cudaGetSymbolAddress((void**)&wh, g_wh);
    cudaGetSymbolAddress((void**)&wl, g_wl);
    cudaGetSymbolAddress((void**)&qh, g_qh);
    cudaGetSymbolAddress((void**)&ql, g_ql);
    cudaGetSymbolAddress((void**)&kh, g_kh);
    cudaGetSymbolAddress((void**)&kl, g_kl);
    cudaGetSymbolAddress((void**)&vh, g_vh);
    cudaGetSymbolAddress((void**)&vl, g_vl);

    dim3 gg(Dn/128, Mn/128);
    int xn4 = Mn*Dn/4, wn4 = Dn*Dn/4;
    int rope_total = Bn*Sn*Hn*32;

    split_kernel<<<(xn4 + 255)/256, 256>>>(x, ah, al, xn4);

    split_kernel<<<(wn4 + 255)/256, 256>>>(wq, wh, wl, wn4);
    gemm_mma<<<gg, 256>>>(ah, al, wh, wl, t);
    rope_kernel<<<(rope_total + 255)/256, 256>>>(t, qh, ql);

    split_kernel<<<(wn4 + 255)/256, 256>>>(wk, wh, wl, wn4);
    gemm_mma<<<gg, 256>>>(ah, al, wh, wl, t);
    rope_kernel<<<(rope_total + 255)/256, 256>>>(t, kh, kl);

    split_kernel<<<(wn4 + 255)/256, 256>>>(wv, wh, wl, wn4);
    gemm_mma<<<gg, 256>>>(ah, al, wh, wl, t);
    vsplit_kernel<<<dim3(Sn/64, Bn*Hn), 256>>>(t, vh, vl);

    attn_mma<<<dim3(Sn/128, Bn*Hn), 256>>>(qh, ql, kh, kl, vh, vl, t);

    split_kernel<<<(xn4 + 255)/256, 256>>>(t, ah, al, xn4);
    split_kernel<<<(wn4 + 255)/256, 256>>>(wo, wh, wl, wn4);
    gemm_mma<<<gg, 256>>>(ah, al, wh, wl, out);
}